// round 15
// baseline (speedup 1.0000x reference)
#include <cuda_runtime.h>
#include <cuda_fp16.h>

#define N_NODES 1000000
#define KH 5
#define NHOP 4
#define OUTF 64
#define BN_EPS 1e-5f

#define SBSHIFT 12
#define SBSIZE 4096
#define NSB 245              // dst superbuckets of 4096 nodes
#define CAP 147456           // per-superbucket capacity (36*4096, PAD multiple)
#define PAD 16384            // bucket length padded to multiple of this (= NSLICE*512*8)
#define NSLICE 4

#define SORT_C 16384
#define SORT_T 1024

// ---- scratch (module-static, allocation-free) ----
__device__ __align__(16) unsigned g_key[(size_t)NSB * CAP];  // src<<12 | dstlo (145 MB)
__device__ __align__(16) __half   g_wh [(size_t)NSB * CAP];  // fp16 weights (72 MB)
__device__ int   g_cur[NSB];                   // write cursors
__device__ int   g_end[NSB];                   // padded region ends
__device__ float g_feat[NHOP][N_NODES];        // hop results 1..4 (16 MB)

__device__ float g_Wp[OUTF * KH];
__device__ float g_bp[OUTF];
__device__ float g_bw[KH];
__device__ float g_G[KH * KH];
__device__ float g_b2;

// ---- per-launch init: zero hop buffers, reset cursors ----
__global__ void __launch_bounds__(256) init_kernel() {
    int i = blockIdx.x * blockDim.x + threadIdx.x;
    float4* p = reinterpret_cast<float4*>(&g_feat[0][0]);
    if (i < (NHOP * N_NODES) / 4) p[i] = make_float4(0.f, 0.f, 0.f, 0.f);
    if (i < NSB) g_cur[i] = i * CAP;
}

// ---- two-pass bucketing sort: count, scan, place (L2 re-read), coalesced out ----
__global__ void __launch_bounds__(SORT_T, 2) sort_kernel(
    const int* __restrict__ src, const int* __restrict__ dst,
    const float* __restrict__ w, int E)
{
    extern __shared__ char sm[];
    unsigned* staged_k = (unsigned*)sm;                       // 64 KB
    __half*   staged_w = (__half*)(sm + SORT_C * 4);          // 32 KB
    __shared__ int scnt[NSB], soff[NSB], gbase[NSB];
    __shared__ int ssc[256];

    int t = threadIdx.x;
    for (int i = t; i < NSB; i += SORT_T) scnt[i] = 0;
    __syncthreads();

    int e0 = blockIdx.x * SORT_C;
    int e1 = min(e0 + SORT_C, E);
    int ev = e0 + ((e1 - e0) & ~3);                // vector-aligned end

    // pass 1: count, int4 loads (dst chunk becomes L2-resident)
    for (int e = e0 + t * 4; e < ev; e += SORT_T * 4) {
        int4 d = __ldg((const int4*)(dst + e));
        atomicAdd(&scnt[d.x >> SBSHIFT], 1);
        atomicAdd(&scnt[d.y >> SBSHIFT], 1);
        atomicAdd(&scnt[d.z >> SBSHIFT], 1);
        atomicAdd(&scnt[d.w >> SBSHIFT], 1);
    }
    for (int e = ev + t; e < e1; e += SORT_T)
        atomicAdd(&scnt[__ldg(&dst[e]) >> SBSHIFT], 1);
    __syncthreads();

    // exclusive scan of scnt (245 -> padded 256), Hillis-Steele
    if (t < 256) ssc[t] = (t < NSB) ? scnt[t] : 0;
    __syncthreads();
#pragma unroll
    for (int o = 1; o < 256; o <<= 1) {
        int v = 0;
        if (t < 256 && t >= o) v = ssc[t - o];
        __syncthreads();
        if (t < 256) ssc[t] += v;
        __syncthreads();
    }
    if (t < NSB) {
        int c = scnt[t];
        soff[t]  = ssc[t] - c;                       // exclusive offset
        gbase[t] = c ? atomicAdd(&g_cur[t], c) : 0;  // claim global range
        scnt[t]  = 0;
    }
    __syncthreads();

    // pass 2: place, vectorized re-read (L2 hit), stage in smem
    for (int e = e0 + t * 4; e < ev; e += SORT_T * 4) {
        int4   d4 = __ldg((const int4*)(dst + e));
        int4   s4 = __ldg((const int4*)(src + e));
        float4 w4 = __ldcs((const float4*)(w + e));
        {
            int b = d4.x >> SBSHIFT;
            int pos = soff[b] + atomicAdd(&scnt[b], 1);
            staged_k[pos] = ((unsigned)s4.x << SBSHIFT) | (unsigned)(d4.x & (SBSIZE - 1));
            staged_w[pos] = __float2half_rn(w4.x);
        }
        {
            int b = d4.y >> SBSHIFT;
            int pos = soff[b] + atomicAdd(&scnt[b], 1);
            staged_k[pos] = ((unsigned)s4.y << SBSHIFT) | (unsigned)(d4.y & (SBSIZE - 1));
            staged_w[pos] = __float2half_rn(w4.y);
        }
        {
            int b = d4.z >> SBSHIFT;
            int pos = soff[b] + atomicAdd(&scnt[b], 1);
            staged_k[pos] = ((unsigned)s4.z << SBSHIFT) | (unsigned)(d4.z & (SBSIZE - 1));
            staged_w[pos] = __float2half_rn(w4.z);
        }
        {
            int b = d4.w >> SBSHIFT;
            int pos = soff[b] + atomicAdd(&scnt[b], 1);
            staged_k[pos] = ((unsigned)s4.w << SBSHIFT) | (unsigned)(d4.w & (SBSIZE - 1));
            staged_w[pos] = __float2half_rn(w4.w);
        }
    }
    for (int e = ev + t; e < e1; e += SORT_T) {
        int d = __ldg(&dst[e]);
        int s = __ldg(&src[e]);
        int b = d >> SBSHIFT;
        int pos = soff[b] + atomicAdd(&scnt[b], 1);
        staged_k[pos] = ((unsigned)s << SBSHIFT) | (unsigned)(d & (SBSIZE - 1));
        staged_w[pos] = __float2half_rn(__ldcs(&w[e]));
    }
    __syncthreads();

    // coalesced segment copy: one warp per bucket segment
    int wid = t >> 5, lane = t & 31;
    for (int b = wid; b < NSB; b += (SORT_T / 32)) {
        int len = scnt[b], s0 = soff[b];
        size_t gb = (size_t)gbase[b];
        size_t cap_end = (size_t)(b + 1) * CAP;
        for (int j = lane; j < len; j += 32) {
            size_t gpos = gb + j;
            if (gpos < cap_end) {                    // capacity safety clamp
                g_key[gpos] = staged_k[s0 + j];
                g_wh[gpos]  = staged_w[s0 + j];
            }
        }
    }
}

// ---- pad each bucket to a multiple of PAD with zero-weight dummies ----
__global__ void __launch_bounds__(512) pad_kernel() {
    int sb = blockIdx.x;
    int e0 = sb * CAP;
    int cur = g_cur[sb];
    int end = e0 + ((cur - e0 + PAD - 1) / PAD) * PAD;   // <= e0 + CAP
    if (threadIdx.x == 0) g_end[sb] = end;
    for (int e = cur + threadIdx.x; e < end; e += 512) {
        g_key[e] = (unsigned)(e & (SBSIZE - 1));         // spread addresses!
        g_wh[e]  = __float2half_rn(0.f);
    }
}

// ---- one SpMV round: 8 edges/thread, dual smem accumulators ----
__global__ void __launch_bounds__(512) prop_kernel(const float* __restrict__ x, int round) {
    __shared__ float acc[2][SBSIZE];
    int sb = blockIdx.x >> 2;
    int sl = blockIdx.x & (NSLICE - 1);
    const float* __restrict__ cur = (round == 0) ? x : g_feat[round - 1];
    float* nxt = g_feat[round];
    int t = threadIdx.x;

    for (int i = t; i < SBSIZE; i += 512) { acc[0][i] = 0.f; acc[1][i] = 0.f; }
    __syncthreads();

    int e0 = sb * CAP;
    int sl_len = (g_end[sb] - e0) >> 2;          // per-slice edges, multiple of 4096
    int s0 = e0 + sl * sl_len;
    const uint4* k4 = (const uint4*)(g_key + s0); // 4 keys per element
    const uint2* h4 = (const uint2*)(g_wh + s0);  // 4 halves per element
    float* __restrict__ ac = acc[t & 1];
    int iters = sl_len >> 12;                     // / 4096 edges per block-iter

    for (int it = 0; it < iters; it++) {
        int idx = it * 1024 + t;
        uint4 ka = __ldcs(&k4[idx]);
        uint4 kb = __ldcs(&k4[idx + 512]);
        uint2 ha = __ldcs(&h4[idx]);
        uint2 hb = __ldcs(&h4[idx + 512]);
        float2 wa01 = __half22float2(*(const __half2*)&ha.x);
        float2 wa23 = __half22float2(*(const __half2*)&ha.y);
        float2 wb01 = __half22float2(*(const __half2*)&hb.x);
        float2 wb23 = __half22float2(*(const __half2*)&hb.y);
        float v0 = __ldcg(&cur[ka.x >> SBSHIFT]) * wa01.x;
        float v1 = __ldcg(&cur[ka.y >> SBSHIFT]) * wa01.y;
        float v2 = __ldcg(&cur[ka.z >> SBSHIFT]) * wa23.x;
        float v3 = __ldcg(&cur[ka.w >> SBSHIFT]) * wa23.y;
        float v4 = __ldcg(&cur[kb.x >> SBSHIFT]) * wb01.x;
        float v5 = __ldcg(&cur[kb.y >> SBSHIFT]) * wb01.y;
        float v6 = __ldcg(&cur[kb.z >> SBSHIFT]) * wb23.x;
        float v7 = __ldcg(&cur[kb.w >> SBSHIFT]) * wb23.y;
        atomicAdd(&ac[ka.x & (SBSIZE - 1)], v0);
        atomicAdd(&ac[ka.y & (SBSIZE - 1)], v1);
        atomicAdd(&ac[ka.z & (SBSIZE - 1)], v2);
        atomicAdd(&ac[ka.w & (SBSIZE - 1)], v3);
        atomicAdd(&ac[kb.x & (SBSIZE - 1)], v4);
        atomicAdd(&ac[kb.y & (SBSIZE - 1)], v5);
        atomicAdd(&ac[kb.z & (SBSIZE - 1)], v6);
        atomicAdd(&ac[kb.w & (SBSIZE - 1)], v7);
    }
    __syncthreads();

    int n0 = sb << SBSHIFT;
    for (int i = t; i < SBSIZE; i += 512) {
        int n = n0 + i;
        if (n < N_NODES) {
            float v = acc[0][i] + acc[1][i];
            if (v != 0.f) atomicAdd(&nxt[n], v);
        }
    }
}

// ---- tiny precompute of centered weights + quadratic-form constants ----
__global__ void precompute_kernel(const float* __restrict__ weight,
                                  const float* __restrict__ bias)
{
    __shared__ float sW[OUTF * KH];
    __shared__ float sb[OUTF];
    int t = threadIdx.x;   // 64 threads
    sb[t] = bias[t];
#pragma unroll
    for (int k = 0; k < KH; k++) sW[t * KH + k] = weight[t * KH + k];
    __syncthreads();
    if (t == 0) {
        float bm = 0.f;
        for (int f = 0; f < OUTF; f++) bm += sb[f];
        bm *= (1.f / OUTF);
        float wm[KH] = {0.f, 0.f, 0.f, 0.f, 0.f};
        for (int f = 0; f < OUTF; f++)
            for (int k = 0; k < KH; k++) wm[k] += sW[f * KH + k];
        for (int k = 0; k < KH; k++) wm[k] *= (1.f / OUTF);

        float b2 = 0.f;
        float bw[KH] = {0.f, 0.f, 0.f, 0.f, 0.f};
        float G[KH * KH];
        for (int i = 0; i < KH * KH; i++) G[i] = 0.f;

        for (int f = 0; f < OUTF; f++) {
            float bp = sb[f] - bm;
            g_bp[f] = bp;
            b2 += bp * bp;
            float wp[KH];
            for (int k = 0; k < KH; k++) {
                wp[k] = sW[f * KH + k] - wm[k];
                g_Wp[f * KH + k] = wp[k];
                bw[k] += bp * wp[k];
            }
            for (int k = 0; k < KH; k++)
                for (int l = 0; l < KH; l++) G[k * KH + l] += wp[k] * wp[l];
        }
        g_b2 = b2;
        for (int k = 0; k < KH; k++) g_bw[k] = bw[k];
        for (int i = 0; i < KH * KH; i++) g_G[i] = G[i];
    }
}

// ---- fused linear + BN(training) + affine. One warp per node. ----
__global__ void __launch_bounds__(256) final_kernel(
    const float* __restrict__ x, const float* __restrict__ gamma,
    const float* __restrict__ beta, float* __restrict__ out)
{
    __shared__ float sWp[OUTF * KH];
    __shared__ float sbp[OUTF];
    __shared__ float sbw[KH], sG[KH * KH];
    __shared__ float sb2;

    int t = threadIdx.x;
    if (t < 64) {
        sbp[t] = g_bp[t];
#pragma unroll
        for (int k = 0; k < KH; k++) sWp[t * KH + k] = g_Wp[t * KH + k];
    } else if (t < 69) {
        sbw[t - 64] = g_bw[t - 64];
    } else if (t < 94) {
        sG[t - 69] = g_G[t - 69];
    } else if (t == 94) {
        sb2 = g_b2;
    }
    __syncthreads();

    int warp = t >> 5;
    int lane = t & 31;
    int n = blockIdx.x * 8 + warp;   // N divisible by 8

    float c[KH];
    c[0] = __ldg(&x[n]);
    c[1] = g_feat[0][n];
    c[2] = g_feat[1][n];
    c[3] = g_feat[2][n];
    c[4] = g_feat[3][n];

    float ss = sb2;
#pragma unroll
    for (int k = 0; k < KH; k++) ss += 2.f * c[k] * sbw[k];
#pragma unroll
    for (int k = 0; k < KH; k++) {
#pragma unroll
        for (int l = 0; l < KH; l++) ss += c[k] * c[l] * sG[k * KH + l];
    }
    float var = ss * (1.f / OUTF);

    float a  = __ldg(&gamma[n]) * rsqrtf(var + BN_EPS);
    float be = __ldg(&beta[n]);

    size_t base = (size_t)n * OUTF;
#pragma unroll
    for (int half = 0; half < 2; half++) {
        int f = lane + half * 32;
        float z = sbp[f];
#pragma unroll
        for (int k = 0; k < KH; k++) z += c[k] * sWp[f * KH + k];
        out[base + f] = a * z + be;
    }
}

extern "C" void kernel_launch(void* const* d_in, const int* in_sizes, int n_in,
                              void* d_out, int out_size)
{
    const float* x      = (const float*)d_in[0];
    const int*   ei     = (const int*)  d_in[1];   // [2, E]
    const float* ew     = (const float*)d_in[2];
    const float* weight = (const float*)d_in[3];   // [64,5,1]
    const float* bias   = (const float*)d_in[4];
    const float* gamma  = (const float*)d_in[5];
    const float* beta   = (const float*)d_in[6];
    float* out = (float*)d_out;

    const int E = in_sizes[2];            // 32,000,000
    const int* src = ei;
    const int* dst = ei + E;

    int sort_smem = SORT_C * 4 + SORT_C * 2;       // keys + halves = 96 KB
    cudaFuncSetAttribute(sort_kernel,
        cudaFuncAttributeMaxDynamicSharedMemorySize, sort_smem);

    init_kernel<<<(NHOP * N_NODES / 4 + 255) / 256, 256>>>();

    int sort_blocks = (E + SORT_C - 1) / SORT_C;
    sort_kernel<<<sort_blocks, SORT_T, sort_smem>>>(src, dst, ew, E);
    pad_kernel<<<NSB, 512>>>();

    for (int r = 0; r < NHOP; r++)
        prop_kernel<<<NSB * NSLICE, 512>>>(x, r);

    precompute_kernel<<<1, 64>>>(weight, bias);
    final_kernel<<<N_NODES / 8, 256>>>(x, gamma, beta, out);
}

// round 16
// speedup vs baseline: 1.0453x; 1.0453x over previous
#include <cuda_runtime.h>
#include <cuda_fp16.h>

#define N_NODES 1000000
#define KH 5
#define NHOP 4
#define OUTF 64
#define BN_EPS 1e-5f

#define SBSHIFT 12
#define SBSIZE 4096
#define NSB 245              // dst superbuckets of 4096 nodes
#define CAP 143360           // per-superbucket capacity (avg 130612, sigma 361)
#define PAD 8192             // bucket length padded to multiple of this (= NSLICE*512*4)
#define NSLICE 4

#define SORT_C 16384
#define SORT_T 1024

// ---- scratch (module-static, allocation-free) ----
__device__ __align__(16) unsigned g_key[(size_t)NSB * CAP];  // src<<12 | dstlo (140 MB)
__device__ __align__(16) __half   g_wh [(size_t)NSB * CAP];  // fp16 weights (70 MB)
__device__ int   g_cur[NSB];                   // write cursors
__device__ int   g_end[NSB];                   // padded region ends
__device__ float g_feat[NHOP][N_NODES];        // hop results 1..4 (16 MB)

__device__ float g_Wp[OUTF * KH];
__device__ float g_bp[OUTF];
__device__ float g_bw[KH];
__device__ float g_G[KH * KH];
__device__ float g_b2;

// ---- per-launch init: zero hop buffers, reset cursors ----
__global__ void __launch_bounds__(256) init_kernel() {
    int i = blockIdx.x * blockDim.x + threadIdx.x;
    float4* p = reinterpret_cast<float4*>(&g_feat[0][0]);
    if (i < (NHOP * N_NODES) / 4) p[i] = make_float4(0.f, 0.f, 0.f, 0.f);
    if (i < NSB) g_cur[i] = i * CAP;
}

// ---- two-pass bucketing sort: count, scan, place (L2 re-read), coalesced out ----
__global__ void __launch_bounds__(SORT_T, 2) sort_kernel(
    const int* __restrict__ src, const int* __restrict__ dst,
    const float* __restrict__ w, int E)
{
    extern __shared__ char sm[];
    unsigned* staged_k = (unsigned*)sm;                       // 64 KB
    __half*   staged_w = (__half*)(sm + SORT_C * 4);          // 32 KB
    __shared__ int scnt[NSB], soff[NSB], gbase[NSB];
    __shared__ int ssc[256];

    int t = threadIdx.x;
    for (int i = t; i < NSB; i += SORT_T) scnt[i] = 0;
    __syncthreads();

    int e0 = blockIdx.x * SORT_C;
    int e1 = min(e0 + SORT_C, E);
    int ev = e0 + ((e1 - e0) & ~3);                // vector-aligned end

    // pass 1: count, int4 loads (dst chunk becomes L2-resident)
    for (int e = e0 + t * 4; e < ev; e += SORT_T * 4) {
        int4 d = __ldg((const int4*)(dst + e));
        atomicAdd(&scnt[d.x >> SBSHIFT], 1);
        atomicAdd(&scnt[d.y >> SBSHIFT], 1);
        atomicAdd(&scnt[d.z >> SBSHIFT], 1);
        atomicAdd(&scnt[d.w >> SBSHIFT], 1);
    }
    for (int e = ev + t; e < e1; e += SORT_T)
        atomicAdd(&scnt[__ldg(&dst[e]) >> SBSHIFT], 1);
    __syncthreads();

    // exclusive scan of scnt (245 -> padded 256), Hillis-Steele
    if (t < 256) ssc[t] = (t < NSB) ? scnt[t] : 0;
    __syncthreads();
#pragma unroll
    for (int o = 1; o < 256; o <<= 1) {
        int v = 0;
        if (t < 256 && t >= o) v = ssc[t - o];
        __syncthreads();
        if (t < 256) ssc[t] += v;
        __syncthreads();
    }
    if (t < NSB) {
        int c = scnt[t];
        soff[t]  = ssc[t] - c;                       // exclusive offset
        gbase[t] = c ? atomicAdd(&g_cur[t], c) : 0;  // claim global range
        scnt[t]  = 0;
    }
    __syncthreads();

    // pass 2: place, vectorized re-read (L2 hit), stage in smem
    for (int e = e0 + t * 4; e < ev; e += SORT_T * 4) {
        int4   d4 = __ldg((const int4*)(dst + e));
        int4   s4 = __ldg((const int4*)(src + e));
        float4 w4 = __ldcs((const float4*)(w + e));
        {
            int b = d4.x >> SBSHIFT;
            int pos = soff[b] + atomicAdd(&scnt[b], 1);
            staged_k[pos] = ((unsigned)s4.x << SBSHIFT) | (unsigned)(d4.x & (SBSIZE - 1));
            staged_w[pos] = __float2half_rn(w4.x);
        }
        {
            int b = d4.y >> SBSHIFT;
            int pos = soff[b] + atomicAdd(&scnt[b], 1);
            staged_k[pos] = ((unsigned)s4.y << SBSHIFT) | (unsigned)(d4.y & (SBSIZE - 1));
            staged_w[pos] = __float2half_rn(w4.y);
        }
        {
            int b = d4.z >> SBSHIFT;
            int pos = soff[b] + atomicAdd(&scnt[b], 1);
            staged_k[pos] = ((unsigned)s4.z << SBSHIFT) | (unsigned)(d4.z & (SBSIZE - 1));
            staged_w[pos] = __float2half_rn(w4.z);
        }
        {
            int b = d4.w >> SBSHIFT;
            int pos = soff[b] + atomicAdd(&scnt[b], 1);
            staged_k[pos] = ((unsigned)s4.w << SBSHIFT) | (unsigned)(d4.w & (SBSIZE - 1));
            staged_w[pos] = __float2half_rn(w4.w);
        }
    }
    for (int e = ev + t; e < e1; e += SORT_T) {
        int d = __ldg(&dst[e]);
        int s = __ldg(&src[e]);
        int b = d >> SBSHIFT;
        int pos = soff[b] + atomicAdd(&scnt[b], 1);
        staged_k[pos] = ((unsigned)s << SBSHIFT) | (unsigned)(d & (SBSIZE - 1));
        staged_w[pos] = __float2half_rn(__ldcs(&w[e]));
    }
    __syncthreads();

    // coalesced segment copy (streaming stores: don't pollute L2)
    int wid = t >> 5, lane = t & 31;
    for (int b = wid; b < NSB; b += (SORT_T / 32)) {
        int len = scnt[b], s0 = soff[b];
        size_t gb = (size_t)gbase[b];
        size_t cap_end = (size_t)(b + 1) * CAP;
        for (int j = lane; j < len; j += 32) {
            size_t gpos = gb + j;
            if (gpos < cap_end) {                    // capacity safety clamp
                __stcs(&g_key[gpos], staged_k[s0 + j]);
                __stcs(&g_wh[gpos],  staged_w[s0 + j]);
            }
        }
    }
}

// ---- pad each bucket to a multiple of PAD with zero-weight dummies ----
__global__ void __launch_bounds__(512) pad_kernel() {
    int sb = blockIdx.x;
    int e0 = sb * CAP;
    int cur = g_cur[sb];
    int end = e0 + ((cur - e0 + PAD - 1) / PAD) * PAD;   // <= e0 + CAP
    if (threadIdx.x == 0) g_end[sb] = end;
    for (int e = cur + threadIdx.x; e < end; e += 512) {
        g_key[e] = (unsigned)(e & (SBSIZE - 1));         // spread addresses!
        g_wh[e]  = __float2half_rn(0.f);
    }
}

// ---- one SpMV round: 4 edges/thread, dual smem accumulators ----
__global__ void __launch_bounds__(512) prop_kernel(const float* __restrict__ x, int round) {
    __shared__ float acc[2][SBSIZE];
    int sb = blockIdx.x >> 2;
    int sl = blockIdx.x & (NSLICE - 1);
    const float* __restrict__ cur = (round == 0) ? x : g_feat[round - 1];
    float* nxt = g_feat[round];
    int t = threadIdx.x;

    for (int i = t; i < SBSIZE; i += 512) { acc[0][i] = 0.f; acc[1][i] = 0.f; }
    __syncthreads();

    int e0 = sb * CAP;
    int sl_len = (g_end[sb] - e0) >> 2;          // per-slice edges, multiple of 2048
    int s0 = e0 + sl * sl_len;
    const uint4* k4 = (const uint4*)(g_key + s0); // 4 keys per element
    const uint2* h4 = (const uint2*)(g_wh + s0);  // 4 halves per element
    float* __restrict__ ac = acc[t & 1];
    int iters = sl_len >> 11;                     // / 2048 edges per block-iter

    for (int it = 0; it < iters; it++) {
        int idx = it * 512 + t;
        uint4 kk = __ldcs(&k4[idx]);
        uint2 hh = __ldcs(&h4[idx]);
        float2 w01 = __half22float2(*(const __half2*)&hh.x);
        float2 w23 = __half22float2(*(const __half2*)&hh.y);
        float v0 = __ldcg(&cur[kk.x >> SBSHIFT]) * w01.x;
        float v1 = __ldcg(&cur[kk.y >> SBSHIFT]) * w01.y;
        float v2 = __ldcg(&cur[kk.z >> SBSHIFT]) * w23.x;
        float v3 = __ldcg(&cur[kk.w >> SBSHIFT]) * w23.y;
        atomicAdd(&ac[kk.x & (SBSIZE - 1)], v0);
        atomicAdd(&ac[kk.y & (SBSIZE - 1)], v1);
        atomicAdd(&ac[kk.z & (SBSIZE - 1)], v2);
        atomicAdd(&ac[kk.w & (SBSIZE - 1)], v3);
    }
    __syncthreads();

    int n0 = sb << SBSHIFT;
    for (int i = t; i < SBSIZE; i += 512) {
        int n = n0 + i;
        if (n < N_NODES) {
            float v = acc[0][i] + acc[1][i];
            if (v != 0.f) atomicAdd(&nxt[n], v);
        }
    }
}

// ---- tiny precompute of centered weights + quadratic-form constants ----
__global__ void precompute_kernel(const float* __restrict__ weight,
                                  const float* __restrict__ bias)
{
    __shared__ float sW[OUTF * KH];
    __shared__ float sb[OUTF];
    int t = threadIdx.x;   // 64 threads
    sb[t] = bias[t];
#pragma unroll
    for (int k = 0; k < KH; k++) sW[t * KH + k] = weight[t * KH + k];
    __syncthreads();
    if (t == 0) {
        float bm = 0.f;
        for (int f = 0; f < OUTF; f++) bm += sb[f];
        bm *= (1.f / OUTF);
        float wm[KH] = {0.f, 0.f, 0.f, 0.f, 0.f};
        for (int f = 0; f < OUTF; f++)
            for (int k = 0; k < KH; k++) wm[k] += sW[f * KH + k];
        for (int k = 0; k < KH; k++) wm[k] *= (1.f / OUTF);

        float b2 = 0.f;
        float bw[KH] = {0.f, 0.f, 0.f, 0.f, 0.f};
        float G[KH * KH];
        for (int i = 0; i < KH * KH; i++) G[i] = 0.f;

        for (int f = 0; f < OUTF; f++) {
            float bp = sb[f] - bm;
            g_bp[f] = bp;
            b2 += bp * bp;
            float wp[KH];
            for (int k = 0; k < KH; k++) {
                wp[k] = sW[f * KH + k] - wm[k];
                g_Wp[f * KH + k] = wp[k];
                bw[k] += bp * wp[k];
            }
            for (int k = 0; k < KH; k++)
                for (int l = 0; l < KH; l++) G[k * KH + l] += wp[k] * wp[l];
        }
        g_b2 = b2;
        for (int k = 0; k < KH; k++) g_bw[k] = bw[k];
        for (int i = 0; i < KH * KH; i++) g_G[i] = G[i];
    }
}

// ---- fused linear + BN(training) + affine. One warp per node. ----
__global__ void __launch_bounds__(256) final_kernel(
    const float* __restrict__ x, const float* __restrict__ gamma,
    const float* __restrict__ beta, float* __restrict__ out)
{
    __shared__ float sWp[OUTF * KH];
    __shared__ float sbp[OUTF];
    __shared__ float sbw[KH], sG[KH * KH];
    __shared__ float sb2;

    int t = threadIdx.x;
    if (t < 64) {
        sbp[t] = g_bp[t];
#pragma unroll
        for (int k = 0; k < KH; k++) sWp[t * KH + k] = g_Wp[t * KH + k];
    } else if (t < 69) {
        sbw[t - 64] = g_bw[t - 64];
    } else if (t < 94) {
        sG[t - 69] = g_G[t - 69];
    } else if (t == 94) {
        sb2 = g_b2;
    }
    __syncthreads();

    int warp = t >> 5;
    int lane = t & 31;
    int n = blockIdx.x * 8 + warp;   // N divisible by 8

    float c[KH];
    c[0] = __ldg(&x[n]);
    c[1] = g_feat[0][n];
    c[2] = g_feat[1][n];
    c[3] = g_feat[2][n];
    c[4] = g_feat[3][n];

    float ss = sb2;
#pragma unroll
    for (int k = 0; k < KH; k++) ss += 2.f * c[k] * sbw[k];
#pragma unroll
    for (int k = 0; k < KH; k++) {
#pragma unroll
        for (int l = 0; l < KH; l++) ss += c[k] * c[l] * sG[k * KH + l];
    }
    float var = ss * (1.f / OUTF);

    float a  = __ldg(&gamma[n]) * rsqrtf(var + BN_EPS);
    float be = __ldg(&beta[n]);

    size_t base = (size_t)n * OUTF;
#pragma unroll
    for (int half = 0; half < 2; half++) {
        int f = lane + half * 32;
        float z = sbp[f];
#pragma unroll
        for (int k = 0; k < KH; k++) z += c[k] * sWp[f * KH + k];
        __stcs(&out[base + f], a * z + be);       // streaming: no L2 pollution
    }
}

extern "C" void kernel_launch(void* const* d_in, const int* in_sizes, int n_in,
                              void* d_out, int out_size)
{
    const float* x      = (const float*)d_in[0];
    const int*   ei     = (const int*)  d_in[1];   // [2, E]
    const float* ew     = (const float*)d_in[2];
    const float* weight = (const float*)d_in[3];   // [64,5,1]
    const float* bias   = (const float*)d_in[4];
    const float* gamma  = (const float*)d_in[5];
    const float* beta   = (const float*)d_in[6];
    float* out = (float*)d_out;

    const int E = in_sizes[2];            // 32,000,000
    const int* src = ei;
    const int* dst = ei + E;

    int sort_smem = SORT_C * 4 + SORT_C * 2;       // keys + halves = 96 KB
    cudaFuncSetAttribute(sort_kernel,
        cudaFuncAttributeMaxDynamicSharedMemorySize, sort_smem);

    init_kernel<<<(NHOP * N_NODES / 4 + 255) / 256, 256>>>();

    int sort_blocks = (E + SORT_C - 1) / SORT_C;
    sort_kernel<<<sort_blocks, SORT_T, sort_smem>>>(src, dst, ew, E);
    pad_kernel<<<NSB, 512>>>();

    for (int r = 0; r < NHOP; r++)
        prop_kernel<<<NSB * NSLICE, 512>>>(x, r);

    precompute_kernel<<<1, 64>>>(weight, bias);
    final_kernel<<<N_NODES / 8, 256>>>(x, gamma, beta, out);
}